// round 5
// baseline (speedup 1.0000x reference)
#include <cuda_runtime.h>
#include <cstdint>

// GausSplatingHead: per-point 3D Gaussian covariance from (scale, quaternion).
// R5: persistent blocks, software-pipelined loads, double-buffered TMA store.
//   - each block loops over tiles (grid-stride); LDGs for tile i+1 issued
//     before computing tile i  -> continuous DRAM read stream
//   - two 12KB output buffers; cp.async.bulk store of tile i drains while
//     tile i+1 computes (wait_group 1 before buffer reuse)

#define TPB  256
#define TILE 512   // points per tile

__device__ __forceinline__ uint32_t smem_u32(const void* p) {
    uint32_t a;
    asm("{ .reg .u64 t; cvta.to.shared.u64 t, %1; cvt.u32.u64 %0, t; }"
        : "=r"(a) : "l"(p));
    return a;
}

__device__ __forceinline__ void cov_from_q(
    float r, float x, float y, float z,
    float s0, float s1, float s2, float* o /*6*/)
{
    float n2 = r * r + x * x + y * y + z * z;
    // R(q/||q||) entries are quadratic in q: fold normalization into the
    // factor 2 -> ss = 2/||q||^2. Algebraically identical to the reference.
    float ss = __fdividef(2.0f, n2);

    float xx = x * x * ss, yy = y * y * ss, zz = z * z * ss;
    float xy = x * y * ss, xz = x * z * ss, yz = y * z * ss;
    float rx = r * x * ss, ry = r * y * ss, rz = r * z * ss;

    float R00 = 1.0f - yy - zz, R01 = xy - rz, R02 = xz + ry;
    float R10 = xy + rz, R11 = 1.0f - xx - zz, R12 = yz - rx;
    float R20 = xz - ry, R21 = yz + rx, R22 = 1.0f - xx - yy;

    float a = s0 * s0, b = s1 * s1, c = s2 * s2;

    o[0] = R00 * R00 * a + R01 * R01 * b + R02 * R02 * c;  // 00
    o[1] = R00 * R10 * a + R01 * R11 * b + R02 * R12 * c;  // 01
    o[2] = R00 * R20 * a + R01 * R21 * b + R02 * R22 * c;  // 02
    o[3] = R10 * R10 * a + R11 * R11 * b + R12 * R12 * c;  // 11
    o[4] = R10 * R20 * a + R11 * R21 * b + R12 * R22 * c;  // 12
    o[5] = R20 * R20 * a + R21 * R21 * b + R22 * R22 * c;  // 22
}

__global__ __launch_bounds__(TPB) void gs_cov_pipe_kernel(
    const float4* __restrict__ scales4,  // [n*3/4]
    const float4* __restrict__ rots4,    // [n]
    float4* __restrict__ out4,           // [n*6/4]
    int n, int ntiles_full)
{
    __shared__ float s_scales[TILE * 3];                       // 6 KB
    __shared__ __align__(16) float s_out[2][TILE * 6];         // 24 KB

    const int tid = threadIdx.x;

    // -------- persistent loop over full tiles --------
    int it = 0;
    // prologue loads for first tile
    float4 q0, q1, sc0, sc1;
    int tile = blockIdx.x;
    if (tile < ntiles_full) {
        int base = tile * TILE;
        size_t sbase = (size_t)base * 3 / 4;
        q0  = rots4[base + tid];
        q1  = rots4[base + TPB + tid];
        sc0 = scales4[sbase + tid];
        sc1 = (tid < 128) ? scales4[sbase + TPB + tid] : make_float4(0, 0, 0, 0);
    }

    for (; tile < ntiles_full; tile += gridDim.x, it++) {
        const int buf = it & 1;
        const int base = tile * TILE;

        // ensure this output buffer's previous TMA store (2 iters ago) is done
        if (tid == 0)
            asm volatile("cp.async.bulk.wait_group 1;" ::: "memory");
        __syncthreads();   // also separates prev compute's s_scales reads

        // stage scales for this tile
        ((float4*)s_scales)[tid] = sc0;
        if (tid < 128) ((float4*)s_scales)[TPB + tid] = sc1;
        __syncthreads();

        // prefetch next tile's inputs while we compute this one
        float4 nq0, nq1, nsc0, nsc1;
        int ntile = tile + gridDim.x;
        if (ntile < ntiles_full) {
            int nbase = ntile * TILE;
            size_t nsbase = (size_t)nbase * 3 / 4;
            nq0  = rots4[nbase + tid];
            nq1  = rots4[nbase + TPB + tid];
            nsc0 = scales4[nsbase + tid];
            nsc1 = (tid < 128) ? scales4[nsbase + TPB + tid]
                               : make_float4(0, 0, 0, 0);
        }

        // compute 2 points, write to this buffer
        float o0[6], o1[6];
        cov_from_q(q0.x, q0.y, q0.z, q0.w,
                   s_scales[3 * tid + 0], s_scales[3 * tid + 1],
                   s_scales[3 * tid + 2], o0);
        {
            int p = TPB + tid;
            cov_from_q(q1.x, q1.y, q1.z, q1.w,
                       s_scales[3 * p + 0], s_scales[3 * p + 1],
                       s_scales[3 * p + 2], o1);
        }

        float2* so2 = (float2*)s_out[buf];
        so2[3 * tid + 0]         = make_float2(o0[0], o0[1]);
        so2[3 * tid + 1]         = make_float2(o0[2], o0[3]);
        so2[3 * tid + 2]         = make_float2(o0[4], o0[5]);
        so2[3 * (TPB + tid) + 0] = make_float2(o1[0], o1[1]);
        so2[3 * (TPB + tid) + 1] = make_float2(o1[2], o1[3]);
        so2[3 * (TPB + tid) + 2] = make_float2(o1[4], o1[5]);
        __syncthreads();

        // one TMA bulk store for the tile (async; drains during next iter)
        if (tid == 0) {
            asm volatile("fence.proxy.async.shared::cta;" ::: "memory");
            const float* gdst = (const float*)out4 + (size_t)base * 6;
            uint32_t saddr = smem_u32(s_out[buf]);
            asm volatile(
                "cp.async.bulk.global.shared::cta.bulk_group [%0], [%1], %2;"
                :: "l"(gdst), "r"(saddr), "n"(TILE * 6 * 4)
                : "memory");
            asm volatile("cp.async.bulk.commit_group;" ::: "memory");
        }

        q0 = nq0; q1 = nq1; sc0 = nsc0; sc1 = nsc1;
    }

    // drain outstanding stores before smem is released
    if (tid == 0)
        asm volatile("cp.async.bulk.wait_group 0;" ::: "memory");

    // -------- tail points (n not multiple of TILE), block 0 only --------
    if (blockIdx.x == 0) {
        const float* scales = (const float*)scales4;
        const float* rots   = (const float*)rots4;
        float* out          = (float*)out4;
        for (int i = ntiles_full * TILE + tid; i < n; i += TPB) {
            float o[6];
            cov_from_q(rots[4 * i + 0], rots[4 * i + 1],
                       rots[4 * i + 2], rots[4 * i + 3],
                       scales[3 * i + 0], scales[3 * i + 1],
                       scales[3 * i + 2], o);
#pragma unroll
            for (int k = 0; k < 6; k++) out[6 * i + k] = o[k];
        }
    }
}

extern "C" void kernel_launch(void* const* d_in, const int* in_sizes, int n_in,
                              void* d_out, int out_size)
{
    const float4* scales = (const float4*)d_in[0];  // [N,3]
    const float4* rots   = (const float4*)d_in[1];  // [N,4]
    float4* out          = (float4*)d_out;          // [N,6]

    int n = in_sizes[0] / 3;
    int ntiles_full = n / TILE;

    // persistent grid: ~7 blocks/SM (30KB smem/block), capped by tile count
    int grid = 148 * 7;
    if (grid > ntiles_full) grid = ntiles_full > 0 ? ntiles_full : 1;

    gs_cov_pipe_kernel<<<grid, TPB>>>(scales, rots, out, n, ntiles_full);
}

// round 6
// speedup vs baseline: 1.0455x; 1.0455x over previous
#include <cuda_runtime.h>
#include <cstdint>

// GausSplatingHead: per-point 3D Gaussian covariance from (scale, quaternion).
// R6 = R4 structure (best kernel time) + streaming cache policies:
//   - inputs loaded with __ldcs (evict-first: touched exactly once)
//   - output TMA bulk store carries L2::cache_hint evict_first so the 123MB
//     write stream doesn't thrash L2 against the read stream in steady state.

#define TPB  256
#define TILE 512   // points per block

__device__ __forceinline__ uint32_t smem_u32(const void* p) {
    uint32_t a;
    asm("{ .reg .u64 t; cvta.to.shared.u64 t, %1; cvt.u32.u64 %0, t; }"
        : "=r"(a) : "l"(p));
    return a;
}

__device__ __forceinline__ void cov_from_q(
    float r, float x, float y, float z,
    float s0, float s1, float s2, float* o /*6*/)
{
    float n2 = r * r + x * x + y * y + z * z;
    // R(q/||q||) entries are quadratic in q: fold normalization into the
    // factor 2 -> ss = 2/||q||^2. Algebraically identical to the reference.
    float ss = __fdividef(2.0f, n2);

    float xx = x * x * ss, yy = y * y * ss, zz = z * z * ss;
    float xy = x * y * ss, xz = x * z * ss, yz = y * z * ss;
    float rx = r * x * ss, ry = r * y * ss, rz = r * z * ss;

    float R00 = 1.0f - yy - zz, R01 = xy - rz, R02 = xz + ry;
    float R10 = xy + rz, R11 = 1.0f - xx - zz, R12 = yz - rx;
    float R20 = xz - ry, R21 = yz + rx, R22 = 1.0f - xx - yy;

    float a = s0 * s0, b = s1 * s1, c = s2 * s2;

    o[0] = R00 * R00 * a + R01 * R01 * b + R02 * R02 * c;  // 00
    o[1] = R00 * R10 * a + R01 * R11 * b + R02 * R12 * c;  // 01
    o[2] = R00 * R20 * a + R01 * R21 * b + R02 * R22 * c;  // 02
    o[3] = R10 * R10 * a + R11 * R11 * b + R12 * R12 * c;  // 11
    o[4] = R10 * R20 * a + R11 * R21 * b + R12 * R22 * c;  // 12
    o[5] = R20 * R20 * a + R21 * R21 * b + R22 * R22 * c;  // 22
}

__global__ __launch_bounds__(TPB) void gs_cov_tma_cs_kernel(
    const float4* __restrict__ scales4,  // [n*3/4]
    const float4* __restrict__ rots4,    // [n]
    float4* __restrict__ out4,           // [n*6/4]
    int n)
{
    __shared__ float s_scales[TILE * 3];                 // 6 KB
    __shared__ __align__(16) float s_out[TILE * 6];      // 12 KB

    const int tid  = threadIdx.x;
    const int base = blockIdx.x * TILE;

    if (base + TILE <= n) {
        // ---- phase 1: streaming loads, all issued up front ----
        size_t sbase = (size_t)base * 3 / 4;             // float4 index
        float4 q0  = __ldcs(&rots4[base + tid]);          // point tid
        float4 q1  = __ldcs(&rots4[base + TPB + tid]);    // point tid+256
        float4 sc0 = __ldcs(&scales4[sbase + tid]);
        float4 sc1 = (tid < 128) ? __ldcs(&scales4[sbase + TPB + tid])
                                 : make_float4(0, 0, 0, 0);

        ((float4*)s_scales)[tid] = sc0;
        if (tid < 128) ((float4*)s_scales)[TPB + tid] = sc1;
        __syncthreads();

        // ---- phase 2: compute 2 points, STS.64 results ----
        float o0[6], o1[6];
        cov_from_q(q0.x, q0.y, q0.z, q0.w,
                   s_scales[3 * tid + 0], s_scales[3 * tid + 1],
                   s_scales[3 * tid + 2], o0);
        {
            int p = TPB + tid;
            cov_from_q(q1.x, q1.y, q1.z, q1.w,
                       s_scales[3 * p + 0], s_scales[3 * p + 1],
                       s_scales[3 * p + 2], o1);
        }

        float2* so2 = (float2*)s_out;
        so2[3 * tid + 0]         = make_float2(o0[0], o0[1]);
        so2[3 * tid + 1]         = make_float2(o0[2], o0[3]);
        so2[3 * tid + 2]         = make_float2(o0[4], o0[5]);
        so2[3 * (TPB + tid) + 0] = make_float2(o1[0], o1[1]);
        so2[3 * (TPB + tid) + 1] = make_float2(o1[2], o1[3]);
        so2[3 * (TPB + tid) + 2] = make_float2(o1[4], o1[5]);
        __syncthreads();

        // ---- phase 3: one TMA bulk store with evict_first L2 policy ----
        if (tid == 0) {
            asm volatile("fence.proxy.async.shared::cta;" ::: "memory");
            const float* gdst = (const float*)out4 + (size_t)base * 6;
            uint32_t saddr = smem_u32(s_out);
            asm volatile(
                "{\n\t"
                ".reg .b64 pol;\n\t"
                "createpolicy.fractional.L2::evict_first.b64 pol, 1.0;\n\t"
                "cp.async.bulk.global.shared::cta.bulk_group.L2::cache_hint"
                " [%0], [%1], %2, pol;\n\t"
                "}"
                :: "l"(gdst), "r"(saddr), "n"(TILE * 6 * 4)
                : "memory");
            asm volatile("cp.async.bulk.commit_group;" ::: "memory");
            asm volatile("cp.async.bulk.wait_group 0;" ::: "memory");
        }
    } else {
        // ---- tail tile (rare): scalar global path ----
        const float* scales = (const float*)scales4;
        const float* rots   = (const float*)rots4;
        float* out          = (float*)out4;
#pragma unroll
        for (int p = 0; p < 2; p++) {
            int i = base + p * TPB + tid;
            if (i < n) {
                float o[6];
                cov_from_q(rots[4 * i + 0], rots[4 * i + 1],
                           rots[4 * i + 2], rots[4 * i + 3],
                           scales[3 * i + 0], scales[3 * i + 1],
                           scales[3 * i + 2], o);
#pragma unroll
                for (int k = 0; k < 6; k++) out[6 * i + k] = o[k];
            }
        }
    }
}

extern "C" void kernel_launch(void* const* d_in, const int* in_sizes, int n_in,
                              void* d_out, int out_size)
{
    const float4* scales = (const float4*)d_in[0];  // [N,3]
    const float4* rots   = (const float4*)d_in[1];  // [N,4]
    float4* out          = (float4*)d_out;          // [N,6]

    int n = in_sizes[0] / 3;
    int blocks = (n + TILE - 1) / TILE;
    gs_cov_tma_cs_kernel<<<blocks, TPB>>>(scales, rots, out, n);
}